// round 16
// baseline (speedup 1.0000x reference)
#include <cuda_runtime.h>
#include <math.h>

#define DD    40
#define SLAB  1600           // 40*40
#define NVOX  64000          // 40^3
#define NB    2
#define KP    2048
#define EPSV  2.0f
#define BIGF  1e12f
#define SENT  1e9f           // real d2 <= 3*39^2 = 4563 << SENT << BIGF
#define TPB   256
#define NBLK  125            // 125*256 threads * 4 voxels = 128000 = NB*NVOX

// Accumulators + ticket (zero-initialized; reset by last block each replay)
__device__ double g_bsum[NB];
__device__ int    g_bcnt[NB];
__device__ int    g_done;

// ---- exact expanding-shell continuation for r >= 2 (cold: P ~ 2^-27) ----
__device__ __noinline__ float nn_d2_from(const float* __restrict__ t,
                                         int z, int y, int x, float m) {
    for (int r = 2; r <= 39; r++) {
        if (m <= (float)(r * r)) break;      // remaining shells have d2 >= r^2
        for (int dz = -r; dz <= r; dz++) {
            int zz = z + dz; if (zz < 0 || zz > 39) continue;
            bool zface = (dz == -r) || (dz == r);
            for (int dy = -r; dy <= r; dy++) {
                int yy = y + dy; if (yy < 0 || yy > 39) continue;
                bool face = zface || (dy == -r) || (dy == r);
                int rowbase = zz * SLAB + yy * DD;
                int d2zy = dz * dz + dy * dy;
                if (face) {
                    for (int dx = -r; dx <= r; dx++) {
                        int xx = x + dx; if (xx < 0 || xx > 39) continue;
                        if (t[rowbase + xx] > 0.0f)
                            m = fminf(m, (float)(d2zy + dx * dx));
                    }
                } else {
                    int xx = x - r;
                    if (xx >= 0 && t[rowbase + xx] > 0.0f)
                        m = fminf(m, (float)(d2zy + r * r));
                    xx = x + r;
                    if (xx <= 39 && t[rowbase + xx] > 0.0f)
                        m = fminf(m, (float)(d2zy + r * r));
                }
            }
        }
    }
    return m;
}

// ---- exact nearest-true d^2: hot unrolled 3x3x3, then cold generic tail ----
__device__ __forceinline__ float nn_d2_exact(const float* __restrict__ t,
                                             int z, int y, int x) {
    int v = z * SLAB + y * DD + x;
    if (t[v] > 0.0f) return 0.0f;            // P = 0.5: done immediately
    float m = BIGF;
    bool zm = z > 0, zp = z < 39, ym = y > 0, yp = y < 39, xm = x > 0, xp = x < 39;
    #pragma unroll
    for (int dz = -1; dz <= 1; dz++) {
        #pragma unroll
        for (int dy = -1; dy <= 1; dy++) {
            #pragma unroll
            for (int dx = -1; dx <= 1; dx++) {
                if (dz == 0 && dy == 0 && dx == 0) continue;
                bool ok = (dz >= 0 || zm) && (dz <= 0 || zp)
                       && (dy >= 0 || ym) && (dy <= 0 || yp)
                       && (dx >= 0 || xm) && (dx <= 0 || xp);
                if (ok && t[v + dz * SLAB + dy * DD + dx] > 0.0f)
                    m = fminf(m, (float)(dz * dz + dy * dy + dx * dx));
            }
        }
    }
    // if any seed in the 27-cube, m <= 3 < 4 <= d2 of everything outside -> exact
    if (m > 3.5f) m = nn_d2_from(t, z, y, x, m);
    return m;
}

__device__ __forceinline__ void proc_voxel(const float* __restrict__ tgt,
                                           float pv, int b, int v,
                                           double& lsum, int& lcnt) {
    if (pv > EPSV) {
        int z = v / SLAB;
        int rem = v - z * SLAB;
        int y = rem / DD;
        int x = rem - y * DD;
        float m = nn_d2_exact(tgt + b * NVOX, z, y, x);
        lsum += (m > SENT) ? 0.0 : (double)sqrtf(m);  // no-true batch -> 0, still counted
        lcnt++;
    }
}

// ============ Single kernel: search + reduce + last-block finalize ============
__global__ void __launch_bounds__(TPB, 1)
k_main(const float* __restrict__ inp, const float* __restrict__ tgt,
       float* __restrict__ out) {
    const int t = threadIdx.x;
    const int gi = blockIdx.x * TPB + t;     // 0..31999, 4 voxels each
    __shared__ double rs0[8], rs1[8];
    __shared__ int    rc0[8], rc1[8];
    __shared__ int    warpSums[8];
    __shared__ int    sIsLast;
    const int lane = t & 31, wid = t >> 5;

    double ls0 = 0.0, ls1 = 0.0;
    int    lc0 = 0,   lc1 = 0;
    {
        int idx4 = gi * 4;                   // base voxel index (global)
        int b = gi / 16000;                  // warp-uniform (16000 % 32 == 0)
        int v = idx4 - b * NVOX;
        float4 p = reinterpret_cast<const float4*>(inp)[gi];
        double lsum = 0.0; int lcnt = 0;
        proc_voxel(tgt, p.x, b, v,     lsum, lcnt);
        proc_voxel(tgt, p.y, b, v + 1, lsum, lcnt);
        proc_voxel(tgt, p.z, b, v + 2, lsum, lcnt);
        proc_voxel(tgt, p.w, b, v + 3, lsum, lcnt);
        if (b == 0) { ls0 = lsum; lc0 = lcnt; }
        else        { ls1 = lsum; lc1 = lcnt; }
    }

    #pragma unroll
    for (int o = 16; o > 0; o >>= 1) {
        ls0 += __shfl_down_sync(0xFFFFFFFFu, ls0, o);
        ls1 += __shfl_down_sync(0xFFFFFFFFu, ls1, o);
        lc0 += __shfl_down_sync(0xFFFFFFFFu, lc0, o);
        lc1 += __shfl_down_sync(0xFFFFFFFFu, lc1, o);
    }
    if (lane == 0) { rs0[wid] = ls0; rs1[wid] = ls1; rc0[wid] = lc0; rc1[wid] = lc1; }
    __syncthreads();
    if (t == 0) {
        double a0 = 0.0, a1 = 0.0; int c0 = 0, c1 = 0;
        #pragma unroll
        for (int w = 0; w < 8; w++) { a0 += rs0[w]; a1 += rs1[w]; c0 += rc0[w]; c1 += rc1[w]; }
        if (c0) { atomicAdd(&g_bsum[0], a0); atomicAdd(&g_bcnt[0], c0); }
        if (c1) { atomicAdd(&g_bsum[1], a1); atomicAdd(&g_bcnt[1], c1); }
        // ticket: release our atomics, then count ourselves done
        __threadfence();
        int prev = atomicAdd(&g_done, 1);
        sIsLast = (prev == NBLK - 1) ? 1 : 0;
    }
    __syncthreads();
    if (!sIsLast) return;

    // ---- last block only: read L2-coherent totals via atomic read ----
    __shared__ double sSum[NB];
    __shared__ int    sCnt[NB];
    if (t == 0) {
        #pragma unroll
        for (int bb = 0; bb < NB; bb++) {
            sSum[bb] = atomicAdd(&g_bsum[bb], 0.0);
            sCnt[bb] = atomicAdd(&g_bcnt[bb], 0);
        }
    }
    __syncthreads();

    // >KP ordered-truncation fallback (first-2048-in-flat-order, matching
    // jnp.nonzero(size=KP)); never taken in practice but exact if it is.
    for (int bb = 0; bb < NB; bb++) {
        if (sCnt[bb] <= KP) continue;
        const float* tg = tgt + bb * NVOX;
        int runningBase = 0;
        double lsum = 0.0; int lcnt = 0;
        for (int chunk = 0; chunk < NVOX; chunk += TPB) {   // 64000 % 256 == 0
            int idx = chunk + t;
            bool pred = inp[bb * NVOX + idx] > EPSV;
            unsigned ball = __ballot_sync(0xFFFFFFFFu, pred);
            int lanePre = __popc(ball & ((1u << lane) - 1u));
            if (lane == 0) warpSums[wid] = __popc(ball);
            __syncthreads();
            int wOff = 0, total = 0;
            #pragma unroll
            for (int w = 0; w < 8; w++) {
                int cc = warpSums[w];
                if (w < wid) wOff += cc;
                total += cc;
            }
            int rank = runningBase + wOff + lanePre;
            if (pred && rank < KP) {
                lcnt++;
                int z = idx / SLAB;
                int rem = idx - z * SLAB;
                int y = rem / DD;
                int x = rem - y * DD;
                float m = nn_d2_exact(tg, z, y, x);
                lsum += (m > SENT) ? 0.0 : (double)sqrtf(m);
            }
            runningBase += total;
            __syncthreads();
        }
        #pragma unroll
        for (int o = 16; o > 0; o >>= 1) {
            lsum += __shfl_down_sync(0xFFFFFFFFu, lsum, o);
            lcnt += __shfl_down_sync(0xFFFFFFFFu, lcnt, o);
        }
        if (lane == 0) { rs0[wid] = lsum; rc0[wid] = lcnt; }
        __syncthreads();
        if (t == 0) {
            double s = 0.0; int cn = 0;
            #pragma unroll
            for (int w = 0; w < 8; w++) { s += rs0[w]; cn += rc0[w]; }
            sSum[bb] = s;                 // overwrite fast-path value
            sCnt[bb] = cn;
        }
        __syncthreads();
    }

    if (t == 0) {
        int    cnt = sCnt[0] + sCnt[1];
        double s   = sSum[0] + sSum[1];
        out[0] = (cnt > 0) ? (float)(s / (double)cnt) : 0.0f;
        // reset for next graph replay (no other block alive; boundary publishes)
        g_bsum[0] = 0.0; g_bsum[1] = 0.0;
        g_bcnt[0] = 0;   g_bcnt[1] = 0;
        g_done = 0;
    }
}

extern "C" void kernel_launch(void* const* d_in, const int* in_sizes, int n_in,
                              void* d_out, int out_size) {
    const float* inp = (const float*)d_in[0];   // "input"  [2,40,40,40]
    const float* tgt = (const float*)d_in[1];   // "target" [2,40,40,40]
    float* out = (float*)d_out;
    k_main<<<NBLK, TPB>>>(inp, tgt, out);
}